// round 6
// baseline (speedup 1.0000x reference)
#include <cuda_runtime.h>
#include <cstdint>

// ROI adaptive average pooling: one WARP per (b, s, channel-group-of-4).
// Phase 1: per-column PREFIX sums over roi rows with boundary snapshots.
//   Band sums are ps[ey]-ps[sy]; all needed prefix rows lie in
//   { floor(k*h/7), floor(k*h/7)+1 : k=0..7 }  (ceil = floor + (mod!=0)).
//   Snapshot slot s (s=0..14) captures the accumulator at row
//   cap(s) = (s>>1)*h/7 + (s&1). Rows past h add clamped junk AFTER the
//   final snapshot (slot 14 at rr==h) -- no per-row predication at all.
// Phase 2: bin = sum over cols of (cs[se][col]-cs[ss][col]) / area.
//
// x:    [B=8, C=64, H=256, W=256] fp32
// rois: [B=8, S=128, 5] int32 (idx, x1, y1, x2, y2); sides in [8,40]
// out:  [B, S*C, 7, 7] fp32

namespace {
constexpr int B  = 8;
constexpr int C  = 64;
constexpr int H  = 256;
constexpr int W  = 256;
constexpr int S  = 128;
constexpr int OH = 7;
constexpr int OW = 7;
constexpr int MAXD = 40;
constexpr int CH = H * W;
constexpr int NSLOT = 16;                 // 15 used + pad

constexpr int NCH = 4;                    // channels per warp
constexpr int WPB = 4;                    // warps per block
constexpr int THREADS = WPB * 32;
constexpr int NTASK = B * S * (C / NCH);  // 16384
constexpr int NBLOCK = NTASK / WPB;       // 4096
}

__global__ void __launch_bounds__(THREADS) roi_pool_prefix_kernel(
    const float* __restrict__ x,
    const int*   __restrict__ rois,
    float*       __restrict__ out)
{
    __shared__ float cs_all[WPB][NCH][NSLOT][MAXD];  // 4*4*16*40*4 = 40960 B

    const int lane = threadIdx.x & 31;
    const int warp = threadIdx.x >> 5;

    const int task = blockIdx.x * WPB + warp;
    const int cg   = task & (C / NCH - 1);
    const int bs   = task >> 4;
    const int b    = bs >> 7;
    const int c0   = cg * NCH;

    const int* r = rois + bs * 5;
    const int x1 = r[1];
    const int y1 = r[2];
    const int w  = r[3] - x1;              // [8,40]
    const int h  = r[4] - y1;              // [8,40]

    const float* p0 = x + (size_t)(b * C + c0) * CH + (size_t)y1 * W + x1;

    float (*cs)[NSLOT][MAXD] = cs_all[warp];

    if (w <= 32) {
        // -------- narrow: one lane-set, unroll 4, fully unpredicated --------
        float a0 = 0.f, a1 = 0.f, a2 = 0.f, a3 = 0.f;
        int slot = 0;
        int cap  = 0;                               // cap(0) = 0

        for (int r0 = 0; r0 <= h; r0 += 4) {
            float v[4][NCH];
            #pragma unroll
            for (int i = 0; i < 4; ++i) {
                const int rr = min(r0 + i, h);      // row h is in-image
                const float* p = p0 + (size_t)rr * W + lane;
                v[i][0] = __ldg(p);
                v[i][1] = __ldg(p + CH);
                v[i][2] = __ldg(p + 2 * CH);
                v[i][3] = __ldg(p + 3 * CH);
            }
            #pragma unroll
            for (int i = 0; i < 4; ++i) {
                const int rr = r0 + i;
                while (slot < 15 && rr == cap) {    // warp-uniform, monotone
                    cs[0][slot][lane] = a0;
                    cs[1][slot][lane] = a1;
                    cs[2][slot][lane] = a2;
                    cs[3][slot][lane] = a3;
                    ++slot;
                    cap = ((slot >> 1) * h) / OH + (slot & 1);
                }
                a0 += v[i][0];
                a1 += v[i][1];
                a2 += v[i][2];
                a3 += v[i][3];
            }
        }
    } else {
        // -------- wide (33..40): two lane-sets, unroll 2, unpredicated ------
        // Clamped second column: lanes with lane+32 >= w duplicate col w-1;
        // their accumulators are value-identical to the owner lane's, so the
        // STS address collision writes identical data (safe).
        const int col2 = min(lane + 32, w - 1);
        float a0 = 0.f, a1 = 0.f, a2 = 0.f, a3 = 0.f;
        float b0 = 0.f, b1 = 0.f, b2 = 0.f, b3 = 0.f;
        int slot = 0;
        int cap  = 0;

        for (int r0 = 0; r0 <= h; r0 += 2) {
            float va[2][NCH], vb[2][NCH];
            #pragma unroll
            for (int i = 0; i < 2; ++i) {
                const int rr = min(r0 + i, h);
                const float* p  = p0 + (size_t)rr * W;
                va[i][0] = __ldg(p + lane);
                va[i][1] = __ldg(p + CH + lane);
                va[i][2] = __ldg(p + 2 * CH + lane);
                va[i][3] = __ldg(p + 3 * CH + lane);
                vb[i][0] = __ldg(p + col2);
                vb[i][1] = __ldg(p + CH + col2);
                vb[i][2] = __ldg(p + 2 * CH + col2);
                vb[i][3] = __ldg(p + 3 * CH + col2);
            }
            #pragma unroll
            for (int i = 0; i < 2; ++i) {
                const int rr = r0 + i;
                while (slot < 15 && rr == cap) {
                    cs[0][slot][lane] = a0;
                    cs[1][slot][lane] = a1;
                    cs[2][slot][lane] = a2;
                    cs[3][slot][lane] = a3;
                    cs[0][slot][col2] = b0;
                    cs[1][slot][col2] = b1;
                    cs[2][slot][col2] = b2;
                    cs[3][slot][col2] = b3;
                    ++slot;
                    cap = ((slot >> 1) * h) / OH + (slot & 1);
                }
                a0 += va[i][0]; a1 += va[i][1]; a2 += va[i][2]; a3 += va[i][3];
                b0 += vb[i][0]; b1 += vb[i][1]; b2 += vb[i][2]; b3 += vb[i][3];
            }
        }
    }
    __syncwarp();

    // ---- phase 2: bins from prefix differences ----
    float* obase = out + (size_t)(bs * C + c0) * (OH * OW);
    for (int t = lane; t < OH * OW; t += 32) {
        const int oy = t / OW;
        const int ox = t - oy * OW;

        const int sx = (ox * w) / OW;
        const int ex = ((ox + 1) * w + (OW - 1)) / OW;
        const int sy = (oy * h) / OH;
        const int ey = ((oy + 1) * h + (OH - 1)) / OH;

        const int m  = (oy + 1) * h;
        const int ss = 2 * oy;                          // ps[floor(oy*h/7)]
        const int se = 2 * (oy + 1) + ((m % OH) ? 1 : 0); // ps[ceil((oy+1)h/7)]

        float q0 = 0.f, q1 = 0.f, q2 = 0.f, q3 = 0.f;
        #pragma unroll 4
        for (int xx = sx; xx < ex; ++xx) {
            q0 += cs[0][se][xx] - cs[0][ss][xx];
            q1 += cs[1][se][xx] - cs[1][ss][xx];
            q2 += cs[2][se][xx] - cs[2][ss][xx];
            q3 += cs[3][se][xx] - cs[3][ss][xx];
        }

        const float inv = 1.0f / (float)((ey - sy) * (ex - sx));
        obase[t]               = q0 * inv;
        obase[t +     OH * OW] = q1 * inv;
        obase[t + 2 * OH * OW] = q2 * inv;
        obase[t + 3 * OH * OW] = q3 * inv;
    }
}

extern "C" void kernel_launch(void* const* d_in, const int* in_sizes, int n_in,
                              void* d_out, int out_size)
{
    const float* x    = (const float*)d_in[0];
    const int*   rois = (const int*)d_in[1];
    float*       out  = (float*)d_out;

    roi_pool_prefix_kernel<<<NBLOCK, THREADS>>>(x, rois, out);
}